// round 4
// baseline (speedup 1.0000x reference)
#include <cuda_runtime.h>
#include <cstdint>

// MaxUnpooling2D: updates [16,64,64,256] f32, mask [16,64,64,256] i32 (flat idx
// into [16,128,128,256]), out [16,128,128,256] f32.
//
// Each pooled cell targets exactly one slot of its private 2x2 window -> no
// duplicates -> plain stores; zero-fill fused (thread writes all 4 window
// positions for its 4 channels).
//
// R4 = R3 retry (R3 bench hit an infra-side container failure): software-
// pipelined grid-stride loop, 8 tiles per thread; next tile's 512B-coalesced
// loads issued before the current tile's stores so loads overlap stores.
// Last-iteration prefetch restructured to avoid reading uninitialized regs.

namespace {
constexpr int ROW   = 2 * 64 * 256;       // 32768  (dy=1 stride in out)
constexpr int COLS  = 256;                // dx=1 stride in out
constexpr int IMG   = 2 * 64 * ROW;       // batch stride in out
constexpr int NGROUPS = 16 * 64 * 64 * (256 / 4);  // 4,194,304 float4 groups
constexpr int THREADS = 256;
constexpr int BLOCKS  = 2048;
constexpr int STRIDE  = BLOCKS * THREADS;          // 524,288
constexpr int ITERS   = NGROUPS / STRIDE;          // 8 (exact)
}

__device__ __forceinline__ int origin_of(int t)
{
    // t = ((b*64 + h)*64 + w)*64 + c4  ->  flat out index of window origin
    int c4 = t & 63;
    int w  = (t >> 6)  & 63;
    int h  = (t >> 12) & 63;
    int b  = t >> 18;
    return b * IMG + (h << 1) * ROW + (w << 1) * COLS + (c4 << 2);
}

__device__ __forceinline__ void scatter_group(float* __restrict__ out,
                                              int o00, float4 v, int4 m)
{
    int d0 = m.x - o00;
    int d1 = m.y - o00 - 1;
    int d2 = m.z - o00 - 2;
    int d3 = m.w - o00 - 3;

    float4 r00 = make_float4(d0 == 0          ? v.x : 0.f,
                             d1 == 0          ? v.y : 0.f,
                             d2 == 0          ? v.z : 0.f,
                             d3 == 0          ? v.w : 0.f);
    float4 r01 = make_float4(d0 == COLS       ? v.x : 0.f,
                             d1 == COLS       ? v.y : 0.f,
                             d2 == COLS       ? v.z : 0.f,
                             d3 == COLS       ? v.w : 0.f);
    float4 r10 = make_float4(d0 == ROW        ? v.x : 0.f,
                             d1 == ROW        ? v.y : 0.f,
                             d2 == ROW        ? v.z : 0.f,
                             d3 == ROW        ? v.w : 0.f);
    float4 r11 = make_float4(d0 == ROW + COLS ? v.x : 0.f,
                             d1 == ROW + COLS ? v.y : 0.f,
                             d2 == ROW + COLS ? v.z : 0.f,
                             d3 == ROW + COLS ? v.w : 0.f);

    *reinterpret_cast<float4*>(out + o00)              = r00;
    *reinterpret_cast<float4*>(out + o00 + COLS)       = r01;
    *reinterpret_cast<float4*>(out + o00 + ROW)        = r10;
    *reinterpret_cast<float4*>(out + o00 + ROW + COLS) = r11;
}

__global__ void __launch_bounds__(THREADS, 8)
max_unpool_kernel(const float4* __restrict__ upd,
                  const int4*  __restrict__ mask,
                  float*       __restrict__ out)
{
    int g = blockIdx.x * THREADS + threadIdx.x;

    // Prologue load for tile 0.
    float4 v = upd[g];
    int4   m = mask[g];

#pragma unroll
    for (int it = 0; it < ITERS; ++it) {
        int g_cur = g;
        float4 v_cur = v;
        int4   m_cur = m;

        // Prefetch next tile before this tile's stores; on the final
        // iteration skip entirely (no uninitialized reads).
        if (it < ITERS - 1) {
            g = g_cur + STRIDE;
            v = upd[g];
            m = mask[g];
        }

        scatter_group(out, origin_of(g_cur), v_cur, m_cur);
    }
}

extern "C" void kernel_launch(void* const* d_in, const int* in_sizes, int n_in,
                              void* d_out, int out_size)
{
    const float4* upd  = reinterpret_cast<const float4*>(d_in[0]);
    const int4*   mask = reinterpret_cast<const int4*>(d_in[1]);
    float*        out  = reinterpret_cast<float*>(d_out);

    max_unpool_kernel<<<BLOCKS, THREADS>>>(upd, mask, out);
}

// round 5
// speedup vs baseline: 1.0648x; 1.0648x over previous
#include <cuda_runtime.h>
#include <cstdint>

// MaxUnpooling2D: updates [16,64,64,256] f32, mask [16,64,64,256] i32 (flat idx
// into [16,128,128,256]), out [16,128,128,256] f32.
//
// Each pooled cell targets exactly one slot of its private 2x2 window -> no
// duplicates -> plain stores; zero-fill fused (thread writes all 4 window
// positions for its channels).
//
// R5: back to the R1 depth-1 structure (R2/R4 showed extra per-thread depth
// monotonically lowers DRAM%), but with 256-bit global accesses (sm_100a
// ld.global.nc.v8 / st.global.v8, 32B aligned). One thread = 8 consecutive
// channels; one warp = one pooled cell's full 256-channel vector, so every
// warp transaction is 1KB fully contiguous and LDG/STG count per byte halves.

namespace {
constexpr int ROW   = 2 * 64 * 256;       // 32768  (dy=1 stride in out)
constexpr int COLS  = 256;                // dx=1 stride in out
constexpr int IMG   = 2 * 64 * ROW;       // batch stride in out
constexpr int NG8   = 16 * 64 * 64 * (256 / 8);   // 2,097,152 8-wide groups
constexpr int THREADS = 256;
constexpr int BLOCKS  = NG8 / THREADS;            // 8192 (exact)
}

__device__ __forceinline__ void ldg256_f(const float* p, float* v)
{
    asm volatile(
        "ld.global.nc.v8.f32 {%0,%1,%2,%3,%4,%5,%6,%7}, [%8];"
        : "=f"(v[0]), "=f"(v[1]), "=f"(v[2]), "=f"(v[3]),
          "=f"(v[4]), "=f"(v[5]), "=f"(v[6]), "=f"(v[7])
        : "l"(p));
}

__device__ __forceinline__ void ldg256_i(const int* p, int* v)
{
    asm volatile(
        "ld.global.nc.v8.b32 {%0,%1,%2,%3,%4,%5,%6,%7}, [%8];"
        : "=r"(v[0]), "=r"(v[1]), "=r"(v[2]), "=r"(v[3]),
          "=r"(v[4]), "=r"(v[5]), "=r"(v[6]), "=r"(v[7])
        : "l"(p));
}

__device__ __forceinline__ void stg256_f(float* p, const float* v)
{
    asm volatile(
        "st.global.v8.f32 [%0], {%1,%2,%3,%4,%5,%6,%7,%8};"
        :: "l"(p),
           "f"(v[0]), "f"(v[1]), "f"(v[2]), "f"(v[3]),
           "f"(v[4]), "f"(v[5]), "f"(v[6]), "f"(v[7])
        : "memory");
}

__global__ void __launch_bounds__(THREADS)
max_unpool_kernel(const float* __restrict__ upd,
                  const int*   __restrict__ mask,
                  float*       __restrict__ out)
{
    int t = blockIdx.x * THREADS + threadIdx.x;

    // t = ((b*64 + h)*64 + w)*32 + c8
    int c8 = t & 31;
    int w  = (t >> 5)  & 31 | ((t >> 5) & 32);   // low 6 bits of (t>>5)
    w      = (t >> 5)  & 63;
    int h  = (t >> 11) & 63;
    int b  = t >> 17;

    // Flat output index of window origin (2h, 2w) at channel c8*8.
    int o00 = b * IMG + (h << 1) * ROW + (w << 1) * COLS + (c8 << 3);

    float v[8];
    int   m[8];
    ldg256_f(upd  + (size_t)t * 8, v);
    ldg256_i(mask + (size_t)t * 8, m);

    int d[8];
#pragma unroll
    for (int j = 0; j < 8; ++j)
        d[j] = m[j] - o00 - j;   // in {0, COLS, ROW, ROW+COLS}

    float r[8];

#pragma unroll
    for (int j = 0; j < 8; ++j) r[j] = (d[j] == 0) ? v[j] : 0.f;
    stg256_f(out + o00, r);

#pragma unroll
    for (int j = 0; j < 8; ++j) r[j] = (d[j] == COLS) ? v[j] : 0.f;
    stg256_f(out + o00 + COLS, r);

#pragma unroll
    for (int j = 0; j < 8; ++j) r[j] = (d[j] == ROW) ? v[j] : 0.f;
    stg256_f(out + o00 + ROW, r);

#pragma unroll
    for (int j = 0; j < 8; ++j) r[j] = (d[j] == ROW + COLS) ? v[j] : 0.f;
    stg256_f(out + o00 + ROW + COLS, r);
}

extern "C" void kernel_launch(void* const* d_in, const int* in_sizes, int n_in,
                              void* d_out, int out_size)
{
    const float* upd  = reinterpret_cast<const float*>(d_in[0]);
    const int*   mask = reinterpret_cast<const int*>(d_in[1]);
    float*       out  = reinterpret_cast<float*>(d_out);

    max_unpool_kernel<<<BLOCKS, THREADS>>>(upd, mask, out);
}

// round 6
// speedup vs baseline: 1.0664x; 1.0015x over previous
#include <cuda_runtime.h>
#include <cstdint>

// MaxUnpooling2D: updates [16,64,64,256] f32, mask [16,64,64,256] i32 (flat idx
// into [16,128,128,256]), out [16,128,128,256] f32.
//
// Each pooled cell targets exactly one slot of its private 2x2 window -> no
// duplicates -> plain stores; zero-fill fused (thread writes all 4 window
// positions for its 4 channels). Depth-1, one float4-group per thread — the
// measured-best skeleton (R1: 59.1us, DRAM 71.7%).
//
// R6: single unconfounded change vs R1 — __stcs (evict-first) on the four
// output stores ONLY. Output is write-once/dead-on-arrival; evict-first lets
// L2 write back dirty lines eagerly instead of bursty capacity evictions
// competing with demand reads. Loads remain plain LDG (best measured).

namespace {
constexpr int ROW   = 2 * 64 * 256;       // 32768  (dy=1 stride in out)
constexpr int COLS  = 256;                // dx=1 stride in out
constexpr int IMG   = 2 * 64 * ROW;       // batch stride in out
constexpr int NGROUPS = 16 * 64 * 64 * (256 / 4);   // 4,194,304 float4 groups
constexpr int THREADS = 256;
constexpr int BLOCKS  = NGROUPS / THREADS;          // 16384
}

__global__ void __launch_bounds__(THREADS, 8)
max_unpool_kernel(const float4* __restrict__ upd,
                  const int4*  __restrict__ mask,
                  float*       __restrict__ out)
{
    int t = blockIdx.x * THREADS + threadIdx.x;

    // t = ((b*64 + h)*64 + w)*64 + c4
    int c4 = t & 63;
    int w  = (t >> 6)  & 63;
    int h  = (t >> 12) & 63;
    int b  = t >> 18;
    int c  = c4 << 2;

    // Flat output index of window origin (2h, 2w) at channel c.
    int o00 = b * IMG + (h << 1) * ROW + (w << 1) * COLS + c;

    float4 v = upd[t];
    int4   m = mask[t];

    // Per-lane offset within window: in {0, COLS, ROW, ROW+COLS}
    int d0 = m.x - o00;
    int d1 = m.y - o00 - 1;
    int d2 = m.z - o00 - 2;
    int d3 = m.w - o00 - 3;

    float4 r00 = make_float4(d0 == 0          ? v.x : 0.f,
                             d1 == 0          ? v.y : 0.f,
                             d2 == 0          ? v.z : 0.f,
                             d3 == 0          ? v.w : 0.f);
    float4 r01 = make_float4(d0 == COLS       ? v.x : 0.f,
                             d1 == COLS       ? v.y : 0.f,
                             d2 == COLS       ? v.z : 0.f,
                             d3 == COLS       ? v.w : 0.f);
    float4 r10 = make_float4(d0 == ROW        ? v.x : 0.f,
                             d1 == ROW        ? v.y : 0.f,
                             d2 == ROW        ? v.z : 0.f,
                             d3 == ROW        ? v.w : 0.f);
    float4 r11 = make_float4(d0 == ROW + COLS ? v.x : 0.f,
                             d1 == ROW + COLS ? v.y : 0.f,
                             d2 == ROW + COLS ? v.z : 0.f,
                             d3 == ROW + COLS ? v.w : 0.f);

    __stcs(reinterpret_cast<float4*>(out + o00),              r00);
    __stcs(reinterpret_cast<float4*>(out + o00 + COLS),       r01);
    __stcs(reinterpret_cast<float4*>(out + o00 + ROW),        r10);
    __stcs(reinterpret_cast<float4*>(out + o00 + ROW + COLS), r11);
}

extern "C" void kernel_launch(void* const* d_in, const int* in_sizes, int n_in,
                              void* d_out, int out_size)
{
    const float4* upd  = reinterpret_cast<const float4*>(d_in[0]);
    const int4*   mask = reinterpret_cast<const int4*>(d_in[1]);
    float*        out  = reinterpret_cast<float*>(d_out);

    max_unpool_kernel<<<BLOCKS, THREADS>>>(upd, mask, out);
}